// round 11
// baseline (speedup 1.0000x reference)
#include <cuda_runtime.h>
#include <cstdint>
#include <cfloat>

// Problem constants (fixed by the reference)
#define NB   8192
#define EMB  768
#define NP   96
#define NK   256
#define ND   8
#define NKP  (NK / 2)        // 128 k-pair steps
#define NGRP (NKP / 2)       // 64 groups of 2 steps = 4 codes

#define THREADS      128
#define ROWS_PER_T   4
#define ROWS_PER_BLK (THREADS * ROWS_PER_T)   // 512
#define GRID_X       (NB / ROWS_PER_BLK)      // 16

#define PAIR_STRIDE  10      // u64 per k-pair record (8 dims + c2 + pad)

typedef unsigned long long u64;

__device__ __forceinline__ u64 ffma2(u64 a, u64 b, u64 c) {
    u64 d;
    asm("fma.rn.f32x2 %0, %1, %2, %3;" : "=l"(d) : "l"(a), "l"(b), "l"(c));
    return d;
}
__device__ __forceinline__ u64 pack2(float lo, float hi) {
    u64 r;
    asm("mov.b64 %0, {%1, %2};" : "=l"(r) : "f"(lo), "f"(hi));
    return r;
}
__device__ __forceinline__ void unpack2(u64 v, float& lo, float& hi) {
    asm("mov.b64 {%0, %1}, %2;" : "=f"(lo), "=f"(hi) : "l"(v));
}

// Row-sequential score chain (used ONLY in the index-resolve pass).
// Each row's accumulation order over dims is identical to the dim-major
// interleaved main loop, so recomputation is bit-identical.
__device__ __forceinline__ u64 score_pair(u64 c2, ulonglong2 q0, ulonglong2 q1,
                                          ulonglong2 q2, ulonglong2 q3,
                                          const u64* vd) {
    u64 acc = c2;
    acc = ffma2(vd[0], q0.x, acc);
    acc = ffma2(vd[1], q0.y, acc);
    acc = ffma2(vd[2], q1.x, acc);
    acc = ffma2(vd[3], q1.y, acc);
    acc = ffma2(vd[4], q2.x, acc);
    acc = ffma2(vd[5], q2.y, acc);
    acc = ffma2(vd[6], q3.x, acc);
    acc = ffma2(vd[7], q3.y, acc);
    return acc;
}

// Dim-major interleaved: 4 rows share the SAME q operand in adjacent
// instructions -> operand-reuse cache kills the 3rd RF bank read (rt 3->2).
#define STEP_DIM(d, qd)                      \
    acc0 = ffma2(vd[0][d], (qd), acc0);      \
    acc1 = ffma2(vd[1][d], (qd), acc1);      \
    acc2 = ffma2(vd[2][d], (qd), acc2);      \
    acc3 = ffma2(vd[3][d], (qd), acc3);

#define SCORE_ALL_ROWS(c2, q0, q1, q2, q3)   \
    acc0 = (c2); acc1 = (c2); acc2 = (c2); acc3 = (c2); \
    STEP_DIM(0, (q0).x)                      \
    STEP_DIM(1, (q0).y)                      \
    STEP_DIM(2, (q1).x)                      \
    STEP_DIM(3, (q1).y)                      \
    STEP_DIM(4, (q2).x)                      \
    STEP_DIM(5, (q2).y)                      \
    STEP_DIM(6, (q3).x)                      \
    STEP_DIM(7, (q3).y)

__global__ __launch_bounds__(THREADS, 6)
void pq_argmin_kernel(const float* __restrict__ vecs,
                      const float* __restrict__ codebook,
                      float* __restrict__ out) {
    // Per k-pair record: d0..d7 packed as (-2*c_{2s,d}, -2*c_{2s+1,d}),
    // then (||c_2s||^2, ||c_2s+1||^2). Stride 10 u64 = 80B.
    __shared__ __align__(16) u64 s_pair[NKP][PAIR_STRIDE];  // 10 KB

    const int p   = blockIdx.y;
    const int tid = threadIdx.x;

    // ---- stage codebook[p] into smem: one k-pair per thread ----
    {
        const int kp = tid;  // THREADS == NKP
        const float4* cb = reinterpret_cast<const float4*>(
            codebook + ((size_t)p * NK + 2 * kp) * ND);
        float4 a0 = cb[0], a1 = cb[1];   // code 2kp
        float4 b0 = cb[2], b1 = cb[3];   // code 2kp+1
        float c2a = a0.x*a0.x + a0.y*a0.y + a0.z*a0.z + a0.w*a0.w
                  + a1.x*a1.x + a1.y*a1.y + a1.z*a1.z + a1.w*a1.w;
        float c2b = b0.x*b0.x + b0.y*b0.y + b0.z*b0.z + b0.w*b0.w
                  + b1.x*b1.x + b1.y*b1.y + b1.z*b1.z + b1.w*b1.w;
        u64* rec = s_pair[kp];
        rec[0] = pack2(-2.f*a0.x, -2.f*b0.x);
        rec[1] = pack2(-2.f*a0.y, -2.f*b0.y);
        rec[2] = pack2(-2.f*a0.z, -2.f*b0.z);
        rec[3] = pack2(-2.f*a0.w, -2.f*b0.w);
        rec[4] = pack2(-2.f*a1.x, -2.f*b1.x);
        rec[5] = pack2(-2.f*a1.y, -2.f*b1.y);
        rec[6] = pack2(-2.f*a1.z, -2.f*b1.z);
        rec[7] = pack2(-2.f*a1.w, -2.f*b1.w);
        rec[8] = pack2(c2a, c2b);
    }
    __syncthreads();

    // ---- load 4 rows' v-slices via ONE base pointer + immediate offsets ----
    const float* vbase =
        vecs + (size_t)(blockIdx.x * ROWS_PER_BLK + tid) * EMB + p * ND;

    // v duplicated into both f32x2 lanes, per row per dim.
    // vd is only ever indexed by compile-time constants.
    u64 vd[ROWS_PER_T][ND];
#pragma unroll
    for (int r = 0; r < ROWS_PER_T; r++) {
        const float4* g = reinterpret_cast<const float4*>(
            vbase + (size_t)r * THREADS * EMB);
        float4 a = g[0], b = g[1];
        vd[r][0] = pack2(a.x, a.x);
        vd[r][1] = pack2(a.y, a.y);
        vd[r][2] = pack2(a.z, a.z);
        vd[r][3] = pack2(a.w, a.w);
        vd[r][4] = pack2(b.x, b.x);
        vd[r][5] = pack2(b.y, b.y);
        vd[r][6] = pack2(b.z, b.z);
        vd[r][7] = pack2(b.w, b.w);
    }

    float best [ROWS_PER_T] = {FLT_MAX, FLT_MAX, FLT_MAX, FLT_MAX};
    int   bestG[ROWS_PER_T] = {0, 0, 0, 0};

    // ---- main loop: 64 groups of 2 pair-steps (4 codes each).
    //      FFMA2s are emitted dim-major across rows (reuse-cache friendly);
    //      argmin bookkeeping (FSETP/SEL) runs once per GROUP. ----
#pragma unroll 1
    for (int g = 0; g < NGRP; g++) {
        const u64* rec0 = s_pair[2 * g];
        const u64* rec1 = s_pair[2 * g + 1];
        u64 acc0, acc1, acc2, acc3;

        // step A (codes 4g, 4g+1)
        const ulonglong2* rp0 = reinterpret_cast<const ulonglong2*>(rec0);
        ulonglong2 qa0 = rp0[0];
        ulonglong2 qa1 = rp0[1];
        ulonglong2 qa2 = rp0[2];
        ulonglong2 qa3 = rp0[3];
        u64 ac2 = rec0[8];

        SCORE_ALL_ROWS(ac2, qa0, qa1, qa2, qa3)

        float m0[ROWS_PER_T];
        {
            float sa, sb;
            unpack2(acc0, sa, sb); m0[0] = fminf(sa, sb);
            unpack2(acc1, sa, sb); m0[1] = fminf(sa, sb);
            unpack2(acc2, sa, sb); m0[2] = fminf(sa, sb);
            unpack2(acc3, sa, sb); m0[3] = fminf(sa, sb);
        }

        // step B (codes 4g+2, 4g+3)
        const ulonglong2* rp1 = reinterpret_cast<const ulonglong2*>(rec1);
        ulonglong2 qb0 = rp1[0];
        ulonglong2 qb1 = rp1[1];
        ulonglong2 qb2 = rp1[2];
        ulonglong2 qb3 = rp1[3];
        u64 bc2 = rec1[8];

        SCORE_ALL_ROWS(bc2, qb0, qb1, qb2, qb3)

        {
            float sa, sb, m;
            unpack2(acc0, sa, sb);
            m = fminf(m0[0], fminf(sa, sb));
            if (m < best[0]) bestG[0] = g;          // strict '<': earliest group on ties
            best[0] = fminf(best[0], m);

            unpack2(acc1, sa, sb);
            m = fminf(m0[1], fminf(sa, sb));
            if (m < best[1]) bestG[1] = g;
            best[1] = fminf(best[1], m);

            unpack2(acc2, sa, sb);
            m = fminf(m0[2], fminf(sa, sb));
            if (m < best[2]) bestG[2] = g;
            best[2] = fminf(best[2], m);

            unpack2(acc3, sa, sb);
            m = fminf(m0[3], fminf(sa, sb));
            if (m < best[3]) bestG[3] = g;
            best[3] = fminf(best[3], m);
        }
    }

    // ---- fused: resolve index inside winning group (bit-exact recompute)
    //      + gather + store, one row at a time. r-loop fully unrolled
    //      (static vd indexing); dynamic indexing touches smem only. ----
    float* obase =
        out + (size_t)(blockIdx.x * ROWS_PER_BLK + tid) * EMB + p * ND;
#pragma unroll
    for (int r = 0; r < ROWS_PER_T; r++) {
        const int s0 = 2 * bestG[r];
        const u64* rec0 = s_pair[s0];
        const u64* rec1 = s_pair[s0 + 1];
        const ulonglong2* rp0 = reinterpret_cast<const ulonglong2*>(rec0);
        const ulonglong2* rp1 = reinterpret_cast<const ulonglong2*>(rec1);
        u64 accA = score_pair(rec0[8], rp0[0], rp0[1], rp0[2], rp0[3], vd[r]);
        u64 accB = score_pair(rec1[8], rp1[0], rp1[1], rp1[2], rp1[3], vd[r]);
        float sa0, sb0, sa1, sb1;
        unpack2(accA, sa0, sb0);
        unpack2(accB, sa1, sb1);
        // ascending priority => lowest k wins exact ties (jnp.argmax semantics)
        int k = 2 * s0 + 3;
        if (sa1 == best[r]) k = 2 * s0 + 2;
        if (sb0 == best[r]) k = 2 * s0 + 1;
        if (sa0 == best[r]) k = 2 * s0;

        // gather winning code; c = (-2c) * -0.5 is bit-exact
        const float* h = reinterpret_cast<const float*>(s_pair[k >> 1]) + (k & 1);
        float4 oa, ob;
        oa.x = -0.5f * h[0];
        oa.y = -0.5f * h[2];
        oa.z = -0.5f * h[4];
        oa.w = -0.5f * h[6];
        ob.x = -0.5f * h[8];
        ob.y = -0.5f * h[10];
        ob.z = -0.5f * h[12];
        ob.w = -0.5f * h[14];
        float4* o = reinterpret_cast<float4*>(obase + (size_t)r * THREADS * EMB);
        o[0] = oa;
        o[1] = ob;
    }
}

extern "C" void kernel_launch(void* const* d_in, const int* in_sizes, int n_in,
                              void* d_out, int out_size) {
    const float* vecs     = (const float*)d_in[0];   // [8192, 768] f32
    const float* codebook = (const float*)d_in[1];   // [96, 256, 8] f32
    float* out            = (float*)d_out;           // [8192, 768] f32

    dim3 grid(GRID_X, NP);
    dim3 block(THREADS);
    pq_argmin_kernel<<<grid, block>>>(vecs, codebook, out);
}

// round 12
// speedup vs baseline: 1.5864x; 1.5864x over previous
#include <cuda_runtime.h>
#include <cstdint>
#include <cfloat>

// Problem constants (fixed by the reference)
#define NB   8192
#define EMB  768
#define NP   96
#define NK   256
#define ND   8
#define NKP  (NK / 2)        // 128 k-pair steps
#define NGRP (NKP / 2)       // 64 groups of 2 steps = 4 codes

#define THREADS      128
#define ROWS_PER_T   4
#define ROWS_PER_BLK (THREADS * ROWS_PER_T)   // 512
#define GRID_X       (NB / ROWS_PER_BLK)      // 16

#define GRP_STRIDE   20      // u64 per group record (8+8 dims + 2 c2 + pad)

typedef unsigned long long u64;

__device__ __forceinline__ u64 ffma2(u64 a, u64 b, u64 c) {
    u64 d;
    asm("fma.rn.f32x2 %0, %1, %2, %3;" : "=l"(d) : "l"(a), "l"(b), "l"(c));
    return d;
}
__device__ __forceinline__ u64 pack2(float lo, float hi) {
    u64 r;
    asm("mov.b64 %0, {%1, %2};" : "=l"(r) : "f"(lo), "f"(hi));
    return r;
}
__device__ __forceinline__ void unpack2(u64 v, float& lo, float& hi) {
    asm("mov.b64 {%0, %1}, %2;" : "=f"(lo), "=f"(hi) : "l"(v));
}

// Exact score chain — serially dependent, so recomputation is bit-identical.
__device__ __forceinline__ u64 score_pair(u64 c2, ulonglong2 q0, ulonglong2 q1,
                                          ulonglong2 q2, ulonglong2 q3,
                                          const u64* vd) {
    u64 acc = c2;
    acc = ffma2(vd[0], q0.x, acc);
    acc = ffma2(vd[1], q0.y, acc);
    acc = ffma2(vd[2], q1.x, acc);
    acc = ffma2(vd[3], q1.y, acc);
    acc = ffma2(vd[4], q2.x, acc);
    acc = ffma2(vd[5], q2.y, acc);
    acc = ffma2(vd[6], q3.x, acc);
    acc = ffma2(vd[7], q3.y, acc);
    return acc;
}

__global__ __launch_bounds__(THREADS, 5)
void pq_argmin_kernel(const float* __restrict__ vecs,
                      const float* __restrict__ codebook,
                      float* __restrict__ out) {
    // Group record (4 codes): [0..7]  dims of step A, packed (-2c_{4g,d}, -2c_{4g+1,d})
    //                         [8..15] dims of step B, packed (-2c_{4g+2,d}, -2c_{4g+3,d})
    //                         [16]    (||c_4g||^2,   ||c_4g+1||^2)
    //                         [17]    (||c_4g+2||^2, ||c_4g+3||^2)
    //                         [18..19] pad. Stride 160B; [16] is 16B-aligned so
    //                         both c2 pairs come in with ONE LDS.128.
    __shared__ __align__(16) u64 s_grp[NGRP][GRP_STRIDE];  // 10.24 KB

    const int p   = blockIdx.y;
    const int tid = threadIdx.x;

    // ---- stage codebook[p]: thread t handles code pair (2t, 2t+1) ----
    {
        const int g    = tid >> 1;   // group
        const int half = tid & 1;    // 0 = step A, 1 = step B
        const float4* cb = reinterpret_cast<const float4*>(
            codebook + ((size_t)p * NK + 2 * tid) * ND);   // coalesced 64B/thread
        float4 a0 = cb[0], a1 = cb[1];   // code 2t
        float4 b0 = cb[2], b1 = cb[3];   // code 2t+1
        float c2a = a0.x*a0.x + a0.y*a0.y + a0.z*a0.z + a0.w*a0.w
                  + a1.x*a1.x + a1.y*a1.y + a1.z*a1.z + a1.w*a1.w;
        float c2b = b0.x*b0.x + b0.y*b0.y + b0.z*b0.z + b0.w*b0.w
                  + b1.x*b1.x + b1.y*b1.y + b1.z*b1.z + b1.w*b1.w;
        u64* rec = s_grp[g] + 8 * half;
        rec[0] = pack2(-2.f*a0.x, -2.f*b0.x);
        rec[1] = pack2(-2.f*a0.y, -2.f*b0.y);
        rec[2] = pack2(-2.f*a0.z, -2.f*b0.z);
        rec[3] = pack2(-2.f*a0.w, -2.f*b0.w);
        rec[4] = pack2(-2.f*a1.x, -2.f*b1.x);
        rec[5] = pack2(-2.f*a1.y, -2.f*b1.y);
        rec[6] = pack2(-2.f*a1.z, -2.f*b1.z);
        rec[7] = pack2(-2.f*a1.w, -2.f*b1.w);
        s_grp[g][16 + half] = pack2(c2a, c2b);
    }
    __syncthreads();

    // ---- load 4 rows' v-slices via ONE base pointer + immediate offsets ----
    const float* vbase =
        vecs + (size_t)(blockIdx.x * ROWS_PER_BLK + tid) * EMB + p * ND;

    // v duplicated into both f32x2 lanes; vd only indexed by constants.
    u64 vd[ROWS_PER_T][ND];
#pragma unroll
    for (int r = 0; r < ROWS_PER_T; r++) {
        const float4* g4 = reinterpret_cast<const float4*>(
            vbase + (size_t)r * THREADS * EMB);
        float4 a = g4[0], b = g4[1];
        vd[r][0] = pack2(a.x, a.x);
        vd[r][1] = pack2(a.y, a.y);
        vd[r][2] = pack2(a.z, a.z);
        vd[r][3] = pack2(a.w, a.w);
        vd[r][4] = pack2(b.x, b.x);
        vd[r][5] = pack2(b.y, b.y);
        vd[r][6] = pack2(b.z, b.z);
        vd[r][7] = pack2(b.w, b.w);
    }

    float best0 = FLT_MAX, best1 = FLT_MAX, best2 = FLT_MAX, best3 = FLT_MAX;
    int   bg0 = 0, bg1 = 0, bg2 = 0, bg3 = 0;

    // ---- main loop: 64 groups of 2 pair-steps (4 codes each).
    //      Proven R10 shape: one record in flight per compute phase. ----
#pragma unroll 1
    for (int g = 0; g < NGRP; g++) {
        const ulonglong2* rp = reinterpret_cast<const ulonglong2*>(s_grp[g]);

        // step A (codes 4g, 4g+1); c2 for BOTH steps arrives in one LDS.128
        ulonglong2 qa0 = rp[0];
        ulonglong2 qa1 = rp[1];
        ulonglong2 qa2 = rp[2];
        ulonglong2 qa3 = rp[3];
        ulonglong2 c2p = rp[8];   // .x = c2 pair of A, .y = c2 pair of B

        float sa, sb;
        u64 acc;
        acc = score_pair(c2p.x, qa0, qa1, qa2, qa3, vd[0]);
        unpack2(acc, sa, sb); float m00 = fminf(sa, sb);
        acc = score_pair(c2p.x, qa0, qa1, qa2, qa3, vd[1]);
        unpack2(acc, sa, sb); float m01 = fminf(sa, sb);
        acc = score_pair(c2p.x, qa0, qa1, qa2, qa3, vd[2]);
        unpack2(acc, sa, sb); float m02 = fminf(sa, sb);
        acc = score_pair(c2p.x, qa0, qa1, qa2, qa3, vd[3]);
        unpack2(acc, sa, sb); float m03 = fminf(sa, sb);

        // step B (codes 4g+2, 4g+3)
        ulonglong2 qb0 = rp[4];
        ulonglong2 qb1 = rp[5];
        ulonglong2 qb2 = rp[6];
        ulonglong2 qb3 = rp[7];

        float m;
        acc = score_pair(c2p.y, qb0, qb1, qb2, qb3, vd[0]);
        unpack2(acc, sa, sb);
        m = fminf(m00, fminf(sa, sb));
        bg0 = (m < best0) ? g : bg0;       // SEL (pred-as-data), earliest g on ties
        best0 = fminf(best0, m);

        acc = score_pair(c2p.y, qb0, qb1, qb2, qb3, vd[1]);
        unpack2(acc, sa, sb);
        m = fminf(m01, fminf(sa, sb));
        bg1 = (m < best1) ? g : bg1;
        best1 = fminf(best1, m);

        acc = score_pair(c2p.y, qb0, qb1, qb2, qb3, vd[2]);
        unpack2(acc, sa, sb);
        m = fminf(m02, fminf(sa, sb));
        bg2 = (m < best2) ? g : bg2;
        best2 = fminf(best2, m);

        acc = score_pair(c2p.y, qb0, qb1, qb2, qb3, vd[3]);
        unpack2(acc, sa, sb);
        m = fminf(m03, fminf(sa, sb));
        bg3 = (m < best3) ? g : bg3;
        best3 = fminf(best3, m);
    }

    const float bestA[ROWS_PER_T] = {best0, best1, best2, best3};
    const int   bgA  [ROWS_PER_T] = {bg0, bg1, bg2, bg3};

    // ---- fused: resolve index inside winning group (bit-exact recompute)
    //      + gather + store, one row at a time. r-loop fully unrolled
    //      (static vd indexing); dynamic indexing touches smem only. ----
    float* obase =
        out + (size_t)(blockIdx.x * ROWS_PER_BLK + tid) * EMB + p * ND;
#pragma unroll
    for (int r = 0; r < ROWS_PER_T; r++) {
        const int gw = bgA[r];
        const ulonglong2* rp = reinterpret_cast<const ulonglong2*>(s_grp[gw]);
        ulonglong2 c2p = rp[8];
        u64 accA = score_pair(c2p.x, rp[0], rp[1], rp[2], rp[3], vd[r]);
        u64 accB = score_pair(c2p.y, rp[4], rp[5], rp[6], rp[7], vd[r]);
        float sa0, sb0, sa1, sb1;
        unpack2(accA, sa0, sb0);
        unpack2(accB, sa1, sb1);
        // ascending priority => lowest k wins exact ties (jnp.argmax semantics)
        int k = 4 * gw + 3;
        if (sa1 == bestA[r]) k = 4 * gw + 2;
        if (sb0 == bestA[r]) k = 4 * gw + 1;
        if (sa0 == bestA[r]) k = 4 * gw;

        // gather winning code; c = (-2c) * -0.5 is bit-exact.
        // code k lives in group k>>2, half (k>>1)&1, lane k&1.
        const float* h = reinterpret_cast<const float*>(
            s_grp[k >> 2] + 8 * ((k >> 1) & 1)) + (k & 1);
        float4 oa, ob;
        oa.x = -0.5f * h[0];
        oa.y = -0.5f * h[2];
        oa.z = -0.5f * h[4];
        oa.w = -0.5f * h[6];
        ob.x = -0.5f * h[8];
        ob.y = -0.5f * h[10];
        ob.z = -0.5f * h[12];
        ob.w = -0.5f * h[14];
        float4* o = reinterpret_cast<float4*>(obase + (size_t)r * THREADS * EMB);
        o[0] = oa;
        o[1] = ob;
    }
}

extern "C" void kernel_launch(void* const* d_in, const int* in_sizes, int n_in,
                              void* d_out, int out_size) {
    const float* vecs     = (const float*)d_in[0];   // [8192, 768] f32
    const float* codebook = (const float*)d_in[1];   // [96, 256, 8] f32
    float* out            = (float*)d_out;           // [8192, 768] f32

    dim3 grid(GRID_X, NP);
    dim3 block(THREADS);
    pq_argmin_kernel<<<grid, block>>>(vecs, codebook, out);
}

// round 13
// speedup vs baseline: 1.5963x; 1.0062x over previous
#include <cuda_runtime.h>
#include <cstdint>
#include <cfloat>

// Problem constants (fixed by the reference)
#define NB   8192
#define EMB  768
#define NP   96
#define NK   256
#define ND   8
#define NKP  (NK / 2)        // 128 k-pair steps
#define NGRP (NKP / 2)       // 64 groups of 2 steps = 4 codes

#define THREADS      128
#define ROWS_PER_T   4
#define ROWS_PER_BLK (THREADS * ROWS_PER_T)   // 512
#define GRID_X       (NB / ROWS_PER_BLK)      // 16

#define GRP_STRIDE   20      // u64 per group record (8+8 dims + 2 c2 + pad)

typedef unsigned long long u64;

__device__ __forceinline__ u64 ffma2(u64 a, u64 b, u64 c) {
    u64 d;
    asm("fma.rn.f32x2 %0, %1, %2, %3;" : "=l"(d) : "l"(a), "l"(b), "l"(c));
    return d;
}
__device__ __forceinline__ u64 pack2(float lo, float hi) {
    u64 r;
    asm("mov.b64 %0, {%1, %2};" : "=l"(r) : "f"(lo), "f"(hi));
    return r;
}
__device__ __forceinline__ void unpack2(u64 v, float& lo, float& hi) {
    asm("mov.b64 {%0, %1}, %2;" : "=f"(lo), "=f"(hi) : "l"(v));
}

// Row-sequential score chain (index-resolve pass only). Per-row dim order is
// identical to the pairwise-interleaved main loop -> bit-identical recompute.
__device__ __forceinline__ u64 score_pair(u64 c2, ulonglong2 q0, ulonglong2 q1,
                                          ulonglong2 q2, ulonglong2 q3,
                                          const u64* vd) {
    u64 acc = c2;
    acc = ffma2(vd[0], q0.x, acc);
    acc = ffma2(vd[1], q0.y, acc);
    acc = ffma2(vd[2], q1.x, acc);
    acc = ffma2(vd[3], q1.y, acc);
    acc = ffma2(vd[4], q2.x, acc);
    acc = ffma2(vd[5], q2.y, acc);
    acc = ffma2(vd[6], q3.x, acc);
    acc = ffma2(vd[7], q3.y, acc);
    return acc;
}

// Pairwise row interleave: adjacent FFMA2s share the SAME q register in the
// same operand slot -> operand-reuse cache drops the q bank read (rt 3->2)
// on the second of each pair. Live state: q block + TWO accumulators.
#define SCORE_2ROWS(accX, accY, c2, q0, q1, q2, q3, vdX, vdY)  \
    accX = (c2); accY = (c2);                                  \
    accX = ffma2((vdX)[0], (q0).x, accX);                      \
    accY = ffma2((vdY)[0], (q0).x, accY);                      \
    accX = ffma2((vdX)[1], (q0).y, accX);                      \
    accY = ffma2((vdY)[1], (q0).y, accY);                      \
    accX = ffma2((vdX)[2], (q1).x, accX);                      \
    accY = ffma2((vdY)[2], (q1).x, accY);                      \
    accX = ffma2((vdX)[3], (q1).y, accX);                      \
    accY = ffma2((vdY)[3], (q1).y, accY);                      \
    accX = ffma2((vdX)[4], (q2).x, accX);                      \
    accY = ffma2((vdY)[4], (q2).x, accY);                      \
    accX = ffma2((vdX)[5], (q2).y, accX);                      \
    accY = ffma2((vdY)[5], (q2).y, accY);                      \
    accX = ffma2((vdX)[6], (q3).x, accX);                      \
    accY = ffma2((vdY)[6], (q3).x, accY);                      \
    accX = ffma2((vdX)[7], (q3).y, accX);                      \
    accY = ffma2((vdY)[7], (q3).y, accY);

__global__ __launch_bounds__(THREADS, 5)
void pq_argmin_kernel(const float* __restrict__ vecs,
                      const float* __restrict__ codebook,
                      float* __restrict__ out) {
    // Group record (4 codes): [0..7] step-A dims, [8..15] step-B dims,
    // [16..17] the two c2 pairs (one LDS.128), [18..19] pad. Stride 160B.
    __shared__ __align__(16) u64 s_grp[NGRP][GRP_STRIDE];  // 10.24 KB

    const int p   = blockIdx.y;
    const int tid = threadIdx.x;

    // ---- stage codebook[p]: thread t handles code pair (2t, 2t+1) ----
    {
        const int g    = tid >> 1;   // group
        const int half = tid & 1;    // 0 = step A, 1 = step B
        const float4* cb = reinterpret_cast<const float4*>(
            codebook + ((size_t)p * NK + 2 * tid) * ND);   // coalesced 64B/thread
        float4 a0 = cb[0], a1 = cb[1];   // code 2t
        float4 b0 = cb[2], b1 = cb[3];   // code 2t+1
        float c2a = a0.x*a0.x + a0.y*a0.y + a0.z*a0.z + a0.w*a0.w
                  + a1.x*a1.x + a1.y*a1.y + a1.z*a1.z + a1.w*a1.w;
        float c2b = b0.x*b0.x + b0.y*b0.y + b0.z*b0.z + b0.w*b0.w
                  + b1.x*b1.x + b1.y*b1.y + b1.z*b1.z + b1.w*b1.w;
        u64* rec = s_grp[g] + 8 * half;
        rec[0] = pack2(-2.f*a0.x, -2.f*b0.x);
        rec[1] = pack2(-2.f*a0.y, -2.f*b0.y);
        rec[2] = pack2(-2.f*a0.z, -2.f*b0.z);
        rec[3] = pack2(-2.f*a0.w, -2.f*b0.w);
        rec[4] = pack2(-2.f*a1.x, -2.f*b1.x);
        rec[5] = pack2(-2.f*a1.y, -2.f*b1.y);
        rec[6] = pack2(-2.f*a1.z, -2.f*b1.z);
        rec[7] = pack2(-2.f*a1.w, -2.f*b1.w);
        s_grp[g][16 + half] = pack2(c2a, c2b);
    }
    __syncthreads();

    // ---- load 4 rows' v-slices via ONE base pointer + immediate offsets ----
    const float* vbase =
        vecs + (size_t)(blockIdx.x * ROWS_PER_BLK + tid) * EMB + p * ND;

    // v duplicated into both f32x2 lanes; vd only indexed by constants.
    u64 vd[ROWS_PER_T][ND];
#pragma unroll
    for (int r = 0; r < ROWS_PER_T; r++) {
        const float4* g4 = reinterpret_cast<const float4*>(
            vbase + (size_t)r * THREADS * EMB);
        float4 a = g4[0], b = g4[1];
        vd[r][0] = pack2(a.x, a.x);
        vd[r][1] = pack2(a.y, a.y);
        vd[r][2] = pack2(a.z, a.z);
        vd[r][3] = pack2(a.w, a.w);
        vd[r][4] = pack2(b.x, b.x);
        vd[r][5] = pack2(b.y, b.y);
        vd[r][6] = pack2(b.z, b.z);
        vd[r][7] = pack2(b.w, b.w);
    }

    float best0 = FLT_MAX, best1 = FLT_MAX, best2 = FLT_MAX, best3 = FLT_MAX;
    int   bg0 = 0, bg1 = 0, bg2 = 0, bg3 = 0;

    // ---- main loop: 64 groups of 2 pair-steps (4 codes each).
    //      R12's proven shape; score phases pairwise-interleaved. ----
#pragma unroll 1
    for (int g = 0; g < NGRP; g++) {
        const ulonglong2* rp = reinterpret_cast<const ulonglong2*>(s_grp[g]);

        // step A (codes 4g, 4g+1); c2 for BOTH steps in one LDS.128
        ulonglong2 qa0 = rp[0];
        ulonglong2 qa1 = rp[1];
        ulonglong2 qa2 = rp[2];
        ulonglong2 qa3 = rp[3];
        ulonglong2 c2p = rp[8];   // .x = c2 pair of A, .y = c2 pair of B

        u64 accX, accY;
        float sa, sb;

        SCORE_2ROWS(accX, accY, c2p.x, qa0, qa1, qa2, qa3, vd[0], vd[1])
        unpack2(accX, sa, sb); float m00 = fminf(sa, sb);
        unpack2(accY, sa, sb); float m01 = fminf(sa, sb);
        SCORE_2ROWS(accX, accY, c2p.x, qa0, qa1, qa2, qa3, vd[2], vd[3])
        unpack2(accX, sa, sb); float m02 = fminf(sa, sb);
        unpack2(accY, sa, sb); float m03 = fminf(sa, sb);

        // step B (codes 4g+2, 4g+3)
        ulonglong2 qb0 = rp[4];
        ulonglong2 qb1 = rp[5];
        ulonglong2 qb2 = rp[6];
        ulonglong2 qb3 = rp[7];

        float m;
        SCORE_2ROWS(accX, accY, c2p.y, qb0, qb1, qb2, qb3, vd[0], vd[1])
        unpack2(accX, sa, sb);
        m = fminf(m00, fminf(sa, sb));
        bg0 = (m < best0) ? g : bg0;       // SEL (pred-as-data), earliest g on ties
        best0 = fminf(best0, m);
        unpack2(accY, sa, sb);
        m = fminf(m01, fminf(sa, sb));
        bg1 = (m < best1) ? g : bg1;
        best1 = fminf(best1, m);

        SCORE_2ROWS(accX, accY, c2p.y, qb0, qb1, qb2, qb3, vd[2], vd[3])
        unpack2(accX, sa, sb);
        m = fminf(m02, fminf(sa, sb));
        bg2 = (m < best2) ? g : bg2;
        best2 = fminf(best2, m);
        unpack2(accY, sa, sb);
        m = fminf(m03, fminf(sa, sb));
        bg3 = (m < best3) ? g : bg3;
        best3 = fminf(best3, m);
    }

    const float bestA[ROWS_PER_T] = {best0, best1, best2, best3};
    const int   bgA  [ROWS_PER_T] = {bg0, bg1, bg2, bg3};

    // ---- fused: resolve index inside winning group (bit-exact recompute)
    //      + gather + store. r-loop fully unrolled (static vd indexing);
    //      dynamic indexing touches smem only. ----
    float* obase =
        out + (size_t)(blockIdx.x * ROWS_PER_BLK + tid) * EMB + p * ND;
#pragma unroll
    for (int r = 0; r < ROWS_PER_T; r++) {
        const int gw = bgA[r];
        const ulonglong2* rp = reinterpret_cast<const ulonglong2*>(s_grp[gw]);
        ulonglong2 c2p = rp[8];
        u64 accA = score_pair(c2p.x, rp[0], rp[1], rp[2], rp[3], vd[r]);
        u64 accB = score_pair(c2p.y, rp[4], rp[5], rp[6], rp[7], vd[r]);
        float sa0, sb0, sa1, sb1;
        unpack2(accA, sa0, sb0);
        unpack2(accB, sa1, sb1);
        // ascending priority => lowest k wins exact ties (jnp.argmax semantics)
        int k = 4 * gw + 3;
        if (sa1 == bestA[r]) k = 4 * gw + 2;
        if (sb0 == bestA[r]) k = 4 * gw + 1;
        if (sa0 == bestA[r]) k = 4 * gw;

        // gather winning code; c = (-2c) * -0.5 is bit-exact.
        // code k: group k>>2, half (k>>1)&1, lane k&1.
        const float* h = reinterpret_cast<const float*>(
            s_grp[k >> 2] + 8 * ((k >> 1) & 1)) + (k & 1);
        float4 oa, ob;
        oa.x = -0.5f * h[0];
        oa.y = -0.5f * h[2];
        oa.z = -0.5f * h[4];
        oa.w = -0.5f * h[6];
        ob.x = -0.5f * h[8];
        ob.y = -0.5f * h[10];
        ob.z = -0.5f * h[12];
        ob.w = -0.5f * h[14];
        float4* o = reinterpret_cast<float4*>(obase + (size_t)r * THREADS * EMB);
        o[0] = oa;
        o[1] = ob;
    }
}

extern "C" void kernel_launch(void* const* d_in, const int* in_sizes, int n_in,
                              void* d_out, int out_size) {
    const float* vecs     = (const float*)d_in[0];   // [8192, 768] f32
    const float* codebook = (const float*)d_in[1];   // [96, 256, 8] f32
    float* out            = (float*)d_out;           // [8192, 768] f32

    dim3 grid(GRID_X, NP);
    dim3 block(THREADS);
    pq_argmin_kernel<<<grid, block>>>(vecs, codebook, out);
}